// round 2
// baseline (speedup 1.0000x reference)
#include <cuda_runtime.h>
#include <cstdint>

#define LATENT   128
#define HIDDEN   256
#define NTYPES   32
#define ETYPES   8
#define TILE_E   64
#define KC       32
#define THREADS  256
#define HSTRIDE  264   // padded row stride for feat/h buffer (16B-aligned rows, conflict-free GEMM2)
#define W2STRIDE 260   // padded row stride for transposed W2

// ---------------- packed f32x2 helpers (Blackwell FFMA2) ----------------
__device__ __forceinline__ unsigned long long fma2(unsigned long long a,
                                                   unsigned long long b,
                                                   unsigned long long c) {
    unsigned long long d;
    asm("fma.rn.f32x2 %0, %1, %2, %3;" : "=l"(d) : "l"(a), "l"(b), "l"(c));
    return d;
}
__device__ __forceinline__ unsigned long long pack2(float lo, float hi) {
    unsigned long long d;
    asm("mov.b64 %0, {%1, %2};" : "=l"(d) : "f"(lo), "f"(hi));
    return d;
}
__device__ __forceinline__ float2 unpack2(unsigned long long v) {
    float2 r;
    asm("mov.b64 {%0, %1}, %2;" : "=f"(r.x), "=f"(r.y) : "l"(v));
    return r;
}

// ---------------- node logits: z @ W_node + b_node ----------------
// block: 256 threads = 32 nodes x 8 type-groups (4 types each)
__global__ void node_kernel(const float* __restrict__ z,
                            const float* __restrict__ Wn,
                            const float* __restrict__ bn,
                            float* __restrict__ out,
                            int n_nodes) {
    __shared__ float ws[LATENT * NTYPES];   // 16 KB, layout [k][t]
    __shared__ float zs[32 * 132];          // 32 rows padded
    __shared__ float bs[NTYPES];

    int tid = threadIdx.x;
    for (int idx = tid; idx < LATENT * NTYPES / 4; idx += THREADS)
        ((float4*)ws)[idx] = ((const float4*)Wn)[idx];
    if (tid < NTYPES) bs[tid] = bn[tid];

    long long nBase = (long long)blockIdx.x * 32;
    for (int idx = tid; idx < 32 * LATENT / 4; idx += THREADS) {
        int n = idx / (LATENT / 4), kk = idx % (LATENT / 4);
        long long gn = nBase + n;
        float4 v = make_float4(0.f, 0.f, 0.f, 0.f);
        if (gn < n_nodes) v = *(const float4*)(z + gn * LATENT + kk * 4);
        *(float4*)(zs + n * 132 + kk * 4) = v;
    }
    __syncthreads();

    int n  = tid >> 3;      // local node 0..31
    int tg = tid & 7;       // type group: types tg*4..tg*4+3
    float a0 = bs[tg * 4 + 0], a1 = bs[tg * 4 + 1];
    float a2 = bs[tg * 4 + 2], a3 = bs[tg * 4 + 3];
    const float* zr = zs + n * 132;
#pragma unroll 8
    for (int k = 0; k < LATENT; k++) {
        float zv = zr[k];
        float4 w = *(const float4*)(ws + k * NTYPES + tg * 4);
        a0 = fmaf(zv, w.x, a0);
        a1 = fmaf(zv, w.y, a1);
        a2 = fmaf(zv, w.z, a2);
        a3 = fmaf(zv, w.w, a3);
    }
    long long gn = nBase + n;
    if (gn < n_nodes) {
        float4 o4 = make_float4(a0, a1, a2, a3);
        *(float4*)(out + gn * NTYPES + tg * 4) = o4;
    }
}

// ---------------- edge MLP ----------------
// block: 256 threads, TILE_E=64 edges.
// main GEMM: [64 x 256(K)] @ W1[256 x 256] with packed f32x2 accumulators.
// thread (eg = tid/32, jg = tid%32): owns 8 edges (eg*8..) x 8 hidden cols (jg*8..)
__global__ void __launch_bounds__(THREADS, 1)
edge_kernel(const float* __restrict__ z,
            const int* __restrict__ ei,          // int32 edge index [2, E]
            const float* __restrict__ W1,
            const float* __restrict__ b1,
            const float* __restrict__ W2,
            const float* __restrict__ b2,
            float* __restrict__ out,
            int n_edges, int n_nodes) {
    extern __shared__ float smem[];
    float* feat = smem;                          // TILE_E * HSTRIDE  (reused for h)
    float* w1s  = feat + TILE_E * HSTRIDE;       // KC * HIDDEN
    float* ws2t = w1s + KC * HIDDEN;             // ETYPES * W2STRIDE

    int tid  = threadIdx.x;
    int lane = tid & 31;
    int warp = tid >> 5;
    long long eBase = (long long)blockIdx.x * TILE_E;

    // stage W2 transposed: ws2t[o][k] = W2[k][o]
    for (int idx = tid; idx < HIDDEN * ETYPES; idx += THREADS) {
        int k = idx / ETYPES, o = idx % ETYPES;
        ws2t[o * W2STRIDE + k] = W2[idx];
    }

    // gather edge features: warp w handles edges w*8..w*8+7; one float4 per lane covers a z row
#pragma unroll
    for (int i = 0; i < 8; i++) {
        long long e = eBase + warp * 8 + i;
        if (e >= n_edges) e = n_edges - 1;   // clamp (pad lanes never written out)
        int r = ei[e];
        int c = ei[(long long)n_edges + e];
        r = min(max(r, 0), n_nodes - 1);     // safety clamp
        c = min(max(c, 0), n_nodes - 1);
        float4 vr = *(const float4*)(z + (long long)r * LATENT + lane * 4);
        float4 vc = *(const float4*)(z + (long long)c * LATENT + lane * 4);
        float* fe = feat + (warp * 8 + i) * HSTRIDE;
        *(float4*)(fe + lane * 4)          = vr;
        *(float4*)(fe + LATENT + lane * 4) = vc;
    }

    int jg = tid & 31;
    int eg = tid >> 5;

    // init accumulators with bias b1 (packed pairs)
    unsigned long long acc[8][4];
    {
        float4 bA = *(const float4*)(b1 + jg * 8);
        float4 bB = *(const float4*)(b1 + jg * 8 + 4);
        unsigned long long i0 = pack2(bA.x, bA.y);
        unsigned long long i1 = pack2(bA.z, bA.w);
        unsigned long long i2 = pack2(bB.x, bB.y);
        unsigned long long i3 = pack2(bB.z, bB.w);
#pragma unroll
        for (int i = 0; i < 8; i++) {
            acc[i][0] = i0; acc[i][1] = i1; acc[i][2] = i2; acc[i][3] = i3;
        }
    }

    const float* feb = feat + eg * 8 * HSTRIDE;

    for (int kk = 0; kk < 2 * LATENT; kk += KC) {
        __syncthreads();
        // stage W1[kk:kk+KC][0:256] -> 8192 floats
        {
            const float4* src = (const float4*)(W1 + kk * HIDDEN);
            float4* dst = (float4*)w1s;
            for (int t = tid; t < KC * HIDDEN / 4; t += THREADS) dst[t] = src[t];
        }
        __syncthreads();
#pragma unroll 4
        for (int kc = 0; kc < KC; kc++) {
            int k = kk + kc;
            const float* wrow = w1s + kc * HIDDEN + jg * 8;
            ulonglong2 wA = *(const ulonglong2*)wrow;        // pairs (j, j+1), (j+2, j+3)
            ulonglong2 wB = *(const ulonglong2*)(wrow + 4);  // pairs (j+4..j+7)
#pragma unroll
            for (int i = 0; i < 8; i++) {
                float f = feb[i * HSTRIDE + k];
                unsigned long long f2 = pack2(f, f);
                acc[i][0] = fma2(f2, wA.x, acc[i][0]);
                acc[i][1] = fma2(f2, wA.y, acc[i][1]);
                acc[i][2] = fma2(f2, wB.x, acc[i][2]);
                acc[i][3] = fma2(f2, wB.y, acc[i][3]);
            }
        }
    }
    __syncthreads();

    // ReLU + store h into feat buffer (reuse)
#pragma unroll
    for (int i = 0; i < 8; i++) {
        float* hrow = feat + (eg * 8 + i) * HSTRIDE + jg * 8;
#pragma unroll
        for (int c = 0; c < 4; c++) {
            float2 v = unpack2(acc[i][c]);
            hrow[c * 2 + 0] = fmaxf(v.x, 0.f);
            hrow[c * 2 + 1] = fmaxf(v.y, 0.f);
        }
    }
    __syncthreads();

    // GEMM2: h[64 x 256] @ W2[256 x 8] + b2 ; thread -> 2 outputs
    int e0 = tid >> 3, o = tid & 7;
    float bo = b2[o];
#pragma unroll
    for (int pass = 0; pass < 2; pass++) {
        int e = e0 + pass * 32;
        const float* hr = feat + e * HSTRIDE;
        const float* wr = ws2t + o * W2STRIDE;
        float a = bo;
#pragma unroll 8
        for (int k = 0; k < HIDDEN; k += 4) {
            float4 hv = *(const float4*)(hr + k);
            float4 wv = *(const float4*)(wr + k);
            a = fmaf(hv.x, wv.x, a);
            a = fmaf(hv.y, wv.y, a);
            a = fmaf(hv.z, wv.z, a);
            a = fmaf(hv.w, wv.w, a);
        }
        long long ge = eBase + e;
        if (ge < n_edges) out[ge * ETYPES + o] = a;
    }
}

// ---------------- launch ----------------
extern "C" void kernel_launch(void* const* d_in, const int* in_sizes, int n_in,
                              void* d_out, int out_size) {
    const float* z  = (const float*)d_in[0];
    const int*   ei = (const int*)d_in[1];      // int32 per harness dtype rules
    const float* Wn = (const float*)d_in[2];
    const float* bn = (const float*)d_in[3];
    const float* W1 = (const float*)d_in[4];
    const float* b1 = (const float*)d_in[5];
    const float* W2 = (const float*)d_in[6];
    const float* b2 = (const float*)d_in[7];

    int n_nodes = in_sizes[0] / LATENT;
    int n_edges = in_sizes[1] / 2;
    float* out = (float*)d_out;

    // node logits first in output, then edge logits
    node_kernel<<<(n_nodes + 31) / 32, THREADS>>>(z, Wn, bn, out, n_nodes);

    size_t smem_bytes = (size_t)(TILE_E * HSTRIDE + KC * HIDDEN + ETYPES * W2STRIDE) * sizeof(float);
    cudaFuncSetAttribute(edge_kernel, cudaFuncAttributeMaxDynamicSharedMemorySize, (int)smem_bytes);
    edge_kernel<<<(n_edges + TILE_E - 1) / TILE_E, THREADS, smem_bytes>>>(
        z, ei, W1, b1, W2, b2, out + (size_t)n_nodes * NTYPES, n_edges, n_nodes);
}